// round 5
// baseline (speedup 1.0000x reference)
#include <cuda_runtime.h>
#include <cuda_bf16.h>

// NDFT type-2: y[b,m] = sum_{k1,k2=-32..31} f_hat[b,k1+32,k2+32]
//                        * exp(-2*pi*i*(k1*x1 + k2*x2))
//
// Radix factorization of k2: k2 = 16a + c - 32, a in [0,4), c in [0,16)
//   e2[k2] = E2c[a] * E2f[c]
//   y = sum_c E2f[c] * S[c],  S[c] = sum_{k1,a} f[k1,16a+c] * (e1[k1]*E2c[a])
//
// Block = 256 threads = 8 warps; each lane = one sample point (32 pts/block),
// each warp owns 8 k1 rows (fatter occupancy: 4096 warps total).
// All shared loads are 32-lane broadcasts. Accumulation and the e1/g twiddle
// math run fully packed (fma.rn.f32x2) with no packing movs in the hot loop.

#define B_DIM 2
#define M_DIM 8192
#define N1 64
#define N2 64
#define K_TOT (N1 * N2)
#define TPB 256
#define NWARP 8
#define PTS 32                               // points per block
#define ROWS_PW (N1 / NWARP)                 // 8 k1 rows per warp
#define BLOCKS_PER_B (M_DIM / PTS)           // 256

typedef unsigned long long ull;

#define PACK2(d, lo, hi) \
    asm("mov.b64 %0, {%1, %2};" : "=l"(d) \
        : "r"(__float_as_uint(lo)), "r"(__float_as_uint(hi)))
#define FMA2(d, a, b, c) \
    asm("fma.rn.f32x2 %0, %1, %2, %3;" : "=l"(d) : "l"(a), "l"(b), "l"(c))
#define MUL2(d, a, b) \
    asm("mul.rn.f32x2 %0, %1, %2;" : "=l"(d) : "l"(a), "l"(b))
#define UNPACK2(lo, hi, s) do { unsigned int _l, _h; \
    asm("mov.b64 {%0, %1}, %2;" : "=r"(_l), "=r"(_h) : "l"(s)); \
    (lo) = __uint_as_float(_l); (hi) = __uint_as_float(_h); } while (0)

__global__ __launch_bounds__(TPB, 3) void ndft_kernel(
    const float* __restrict__ x,      // [B, M, 2]
    const float* __restrict__ f_hat,  // [B, 64, 64]
    float* __restrict__ out,
    const int real_only)
{
    __shared__ __align__(16) float sf[K_TOT];    // 16 KB coefficients
    __shared__ float2 sy[NWARP][PTS];            // per-warp partials (2 KB)

    const int b    = blockIdx.x / BLOCKS_PER_B;
    const int mblk = blockIdx.x % BLOCKS_PER_B;
    const int tid  = threadIdx.x;
    const int w    = tid >> 5;                   // warp id: k1 chunk
    const int lane = tid & 31;
    const int m    = mblk * PTS + lane;          // this lane's point

    // cooperative load of f_hat[b] into shared
    {
        const float4* src = reinterpret_cast<const float4*>(f_hat + b * K_TOT);
        float4* dst = reinterpret_cast<float4*>(sf);
        #pragma unroll
        for (int i = tid; i < K_TOT / 4; i += TPB)
            dst[i] = src[i];
    }
    __syncthreads();

    const float2 xv = reinterpret_cast<const float2*>(x)[b * M_DIM + m];
    const float x1 = xv.x, x2 = xv.y;

    // ---- twiddles (sincospif: arg in units of pi, exact range reduction) ----
    float w1r, w1i;                   // w1 = exp(-2*pi*i*x1)
    sincospif(-2.0f * x1, &w1i, &w1r);
    // e1 anchor for this warp: k1start = 8*w - 32 -> angle/pi = (64 - 16*w)*x1
    float e1r, e1i;
    sincospif((64.0f - 16.0f * (float)w) * x1, &e1i, &e1r);
    float w2r, w2i;                   // w2 = exp(-2*pi*i*x2)
    sincospif(-2.0f * x2, &w2i, &w2r);
    float W16r, W16i;                 // W16 = w2^16 = exp(-32*pi*i*x2)
    sincospif(-32.0f * x2, &W16i, &W16r);
    float C0r, C0i;                   // E2c[0] = exp(-2*pi*i*(-32)*x2)
    sincospif(64.0f * x2, &C0i, &C0r);

    // Packed splats for the hot loop
    ull e1rr, e1ii;                   // (e1r,e1r), (e1i,e1i)
    PACK2(e1rr, e1r, e1r);
    PACK2(e1ii, e1i, e1i);
    ull w1rr, w1ii, nw1ii;            // w1 splats (+ negated imag)
    PACK2(w1rr, w1r, w1r);
    PACK2(w1ii, w1i, w1i);
    PACK2(nw1ii, -w1i, -w1i);

    // E2c[a] = C0 * W16^a, a in [0,4): splats (crr, cii, ncii)
    ull crr[4], cii[4], ncii[4];
    {
        float cr = C0r, ci = C0i;
        #pragma unroll
        for (int a = 0; a < 4; ++a) {
            PACK2(crr[a], cr, cr);
            PACK2(cii[a], ci, ci);
            PACK2(ncii[a], -ci, -ci);
            const float t = cr * W16r - ci * W16i;
            ci = cr * W16i + ci * W16r;
            cr = t;
        }
    }

    // packed accumulators over c in [0,16): pair p holds (c=2p, c=2p+1)
    ull sr2[8], si2[8];
    #pragma unroll
    for (int p = 0; p < 8; ++p) { sr2[p] = 0ull; si2[p] = 0ull; }

    const ulonglong2* frow =
        reinterpret_cast<const ulonglong2*>(sf + (w * ROWS_PW) * N2);

    #pragma unroll 1
    for (int i1 = 0; i1 < ROWS_PW; ++i1) {
        #pragma unroll
        for (int a = 0; a < 4; ++a) {
            // g = e1 * E2c[a]: 4 packed ops, no movs
            ull grr, gii, t0, t1;
            MUL2(t0, e1rr, crr[a]);
            FMA2(grr, e1ii, ncii[a], t0);   // gr = e1r*cr - e1i*ci
            MUL2(t1, e1rr, cii[a]);
            FMA2(gii, e1ii, crr[a], t1);    // gi = e1r*ci + e1i*cr

            #pragma unroll
            for (int j = 0; j < 4; ++j) {
                // f[row, 16a + 4j .. +3]: one broadcast LDS.128
                const ulonglong2 f = frow[a * 4 + j];
                FMA2(sr2[2*j],   f.x, grr, sr2[2*j]);
                FMA2(si2[2*j],   f.x, gii, si2[2*j]);
                FMA2(sr2[2*j+1], f.y, grr, sr2[2*j+1]);
                FMA2(si2[2*j+1], f.y, gii, si2[2*j+1]);
            }
        }

        // e1 *= w1, fully packed (8-step chain, anchored per warp)
        {
            ull t0, t1, ne1rr, ne1ii;
            MUL2(t0, e1rr, w1rr);
            FMA2(ne1rr, e1ii, nw1ii, t0);
            MUL2(t1, e1rr, w1ii);
            FMA2(ne1ii, e1ii, w1rr, t1);
            e1rr = ne1rr; e1ii = ne1ii;
        }
        frow += N2 / 4;   // next row (16 ulonglong2 per row)
    }

    // ---- tail: y_partial = sum_c E2f[c] * S[c],  E2f[c] = w2^c ----
    float yr = 0.0f, yi = 0.0f;
    {
        float fr = 1.0f, fi = 0.0f;   // E2f[c] recurrence
        #pragma unroll
        for (int p = 0; p < 8; ++p) {
            float s0r, s1r, s0i, s1i;
            UNPACK2(s0r, s1r, sr2[p]);
            UNPACK2(s0i, s1i, si2[p]);
            // c = 2p
            yr += fr * s0r - fi * s0i;
            yi += fr * s0i + fi * s0r;
            float t = fr * w2r - fi * w2i;
            fi = fr * w2i + fi * w2r;
            fr = t;
            // c = 2p + 1
            yr += fr * s1r - fi * s1i;
            yi += fr * s1i + fi * s1r;
            t = fr * w2r - fi * w2i;
            fi = fr * w2i + fi * w2r;
            fr = t;
        }
    }

    // ---- cross-warp reduction ----
    sy[w][lane] = make_float2(yr, yi);
    __syncthreads();

    if (tid < PTS) {
        float2 acc = sy[0][tid];
        #pragma unroll
        for (int ww = 1; ww < NWARP; ++ww) {
            acc.x += sy[ww][tid].x;
            acc.y += sy[ww][tid].y;
        }
        const int mo = mblk * PTS + tid;
        if (real_only) {
            out[b * M_DIM + mo] = acc.x;
        } else {
            reinterpret_cast<float2*>(out)[b * M_DIM + mo] = acc;
        }
    }
}

extern "C" void kernel_launch(void* const* d_in, const int* in_sizes, int n_in,
                              void* d_out, int out_size) {
    // Select inputs by element count (metadata order may differ):
    //   x: 2*8192*2 = 32768, f_hat: 2*64*64 = 8192
    const float* x;
    const float* f_hat;
    if (in_sizes[0] == B_DIM * M_DIM * 2) {
        x = (const float*)d_in[0];
        f_hat = (const float*)d_in[1];
    } else {
        x = (const float*)d_in[1];
        f_hat = (const float*)d_in[0];
    }

    float* out = (float*)d_out;
    const int real_only = (out_size == B_DIM * M_DIM) ? 1 : 0;

    ndft_kernel<<<B_DIM * BLOCKS_PER_B, TPB>>>(x, f_hat, out, real_only);
}

// round 6
// speedup vs baseline: 1.0021x; 1.0021x over previous
#include <cuda_runtime.h>
#include <cuda_bf16.h>

// NDFT type-2: y[b,m] = sum_{k1,k2=-32..31} f_hat[b,k1+32,k2+32]
//                        * exp(-2*pi*i*(k1*x1 + k2*x2))
//
// Radix on k2: k2 = 16a + c - 32, a in [0,4), c in [0,16).
// Warp w of 8 owns (a = w&3, k1 half h = w>>2). Its running twiddle
//   g(row) = exp(-2*pi*i*(k1*x1 + (16a-32)*x2)),  g *= w1 per row,
// folds e1 AND E2c into ONE recurrence -> hot loop is 4 g-update ops +
// 4 broadcast LDS.128 + 16 packed acc FMA2 per row. Tail applies
// E2f[c] = w2^c and reduces across the 8 warps via smem.

#define B_DIM 2
#define M_DIM 8192
#define N1 64
#define N2 64
#define K_TOT (N1 * N2)
#define TPB 256
#define NWARP 8
#define PTS 32                               // points per block
#define BLOCKS_PER_B (M_DIM / PTS)           // 256

typedef unsigned long long ull;

#define PACK2(d, lo, hi) \
    asm("mov.b64 %0, {%1, %2};" : "=l"(d) \
        : "r"(__float_as_uint(lo)), "r"(__float_as_uint(hi)))
#define FMA2(d, a, b, c) \
    asm("fma.rn.f32x2 %0, %1, %2, %3;" : "=l"(d) : "l"(a), "l"(b), "l"(c))
#define MUL2(d, a, b) \
    asm("mul.rn.f32x2 %0, %1, %2;" : "=l"(d) : "l"(a), "l"(b))
#define UNPACK2(lo, hi, s) do { unsigned int _l, _h; \
    asm("mov.b64 {%0, %1}, %2;" : "=r"(_l), "=r"(_h) : "l"(s)); \
    (lo) = __uint_as_float(_l); (hi) = __uint_as_float(_h); } while (0)

__global__ __launch_bounds__(TPB) void ndft_kernel(
    const float* __restrict__ x,      // [B, M, 2]
    const float* __restrict__ f_hat,  // [B, 64, 64]
    float* __restrict__ out,
    const int real_only)
{
    __shared__ __align__(16) float sf[K_TOT];    // 16 KB coefficients
    __shared__ float2 sy[NWARP][PTS];            // per-warp partials

    const int b    = blockIdx.x / BLOCKS_PER_B;
    const int mblk = blockIdx.x % BLOCKS_PER_B;
    const int tid  = threadIdx.x;
    const int w    = tid >> 5;
    const int lane = tid & 31;
    const int a    = w & 3;                      // radix digit of k2
    const int h    = w >> 2;                     // k1 half: rows 32h..32h+31
    const int m    = mblk * PTS + lane;          // this lane's point

    // cooperative load of f_hat[b] into shared
    {
        const float4* src = reinterpret_cast<const float4*>(f_hat + b * K_TOT);
        float4* dst = reinterpret_cast<float4*>(sf);
        #pragma unroll
        for (int i = tid; i < K_TOT / 4; i += TPB)
            dst[i] = src[i];
    }
    __syncthreads();

    const float2 xv = reinterpret_cast<const float2*>(x)[b * M_DIM + m];
    const float x1 = xv.x, x2 = xv.y;

    // ---- twiddles (sincospif: arg in units of pi, exact range reduction) ----
    float w1r, w1i;                    // w1 = exp(-2*pi*i*x1)
    sincospif(-2.0f * x1, &w1i, &w1r);
    // e1 anchor: k1start = 32h - 32 -> angle/pi = (64 - 64h)*x1
    float ar, ai;
    sincospif((64.0f - 64.0f * (float)h) * x1, &ai, &ar);
    // E2c[a] = exp(-2*pi*i*(16a-32)*x2) -> angle/pi = (64 - 32a)*x2
    float cr, ci;
    sincospif((64.0f - 32.0f * (float)a) * x2, &ci, &cr);
    float w2r, w2i;                    // w2 = exp(-2*pi*i*x2), for the tail
    sincospif(-2.0f * x2, &w2i, &w2r);

    // g0 = anchor * E2c[a]
    const float g0r = ar * cr - ai * ci;
    const float g0i = ar * ci + ai * cr;

    // packed splats for the hot loop
    ull grr, gii;
    PACK2(grr, g0r, g0r);
    PACK2(gii, g0i, g0i);
    ull w1rr, w1ii, nw1ii;
    PACK2(w1rr, w1r, w1r);
    PACK2(w1ii, w1i, w1i);
    PACK2(nw1ii, -w1i, -w1i);

    // packed accumulators: pair p holds local c = (2p, 2p+1)
    ull sr2[8], si2[8];
    #pragma unroll
    for (int p = 0; p < 8; ++p) { sr2[p] = 0ull; si2[p] = 0ull; }

    // this warp's f slice: rows 32h.., columns 16a..16a+15
    const ulonglong2* frow =
        reinterpret_cast<const ulonglong2*>(sf + (h * 32) * N2 + a * 16);

    #pragma unroll 4
    for (int i1 = 0; i1 < 32; ++i1) {
        const ulonglong2 f0 = frow[0];   // c = 0..3   (broadcast LDS.128)
        const ulonglong2 f1 = frow[1];   // c = 4..7
        const ulonglong2 f2 = frow[2];   // c = 8..11
        const ulonglong2 f3 = frow[3];   // c = 12..15

        FMA2(sr2[0], f0.x, grr, sr2[0]);
        FMA2(si2[0], f0.x, gii, si2[0]);
        FMA2(sr2[1], f0.y, grr, sr2[1]);
        FMA2(si2[1], f0.y, gii, si2[1]);
        FMA2(sr2[2], f1.x, grr, sr2[2]);
        FMA2(si2[2], f1.x, gii, si2[2]);
        FMA2(sr2[3], f1.y, grr, sr2[3]);
        FMA2(si2[3], f1.y, gii, si2[3]);
        FMA2(sr2[4], f2.x, grr, sr2[4]);
        FMA2(si2[4], f2.x, gii, si2[4]);
        FMA2(sr2[5], f2.y, grr, sr2[5]);
        FMA2(si2[5], f2.y, gii, si2[5]);
        FMA2(sr2[6], f3.x, grr, sr2[6]);
        FMA2(si2[6], f3.x, gii, si2[6]);
        FMA2(sr2[7], f3.y, grr, sr2[7]);
        FMA2(si2[7], f3.y, gii, si2[7]);

        // g *= w1 (advance k1 by one row); 32-step chain, sincospif-anchored
        ull t0, t1, ngrr;
        MUL2(t0, grr, w1rr);
        FMA2(ngrr, gii, nw1ii, t0);     // gr' = gr*w1r - gi*w1i
        MUL2(t1, grr, w1ii);
        FMA2(gii, gii, w1rr, t1);       // gi' = gr*w1i + gi*w1r
        grr = ngrr;

        frow += N2 / 4;                  // next row
    }

    // ---- tail: y_w = sum_c E2f[c] * S[c], E2f[c] = w2^c (local c) ----
    float yr = 0.0f, yi = 0.0f;
    {
        float fr = 1.0f, fi = 0.0f;
        #pragma unroll
        for (int p = 0; p < 8; ++p) {
            float s0r, s1r, s0i, s1i;
            UNPACK2(s0r, s1r, sr2[p]);
            UNPACK2(s0i, s1i, si2[p]);
            yr += fr * s0r - fi * s0i;           // c = 2p
            yi += fr * s0i + fi * s0r;
            float t = fr * w2r - fi * w2i;
            fi = fr * w2i + fi * w2r;
            fr = t;
            yr += fr * s1r - fi * s1i;           // c = 2p+1
            yi += fr * s1i + fi * s1r;
            t = fr * w2r - fi * w2i;
            fi = fr * w2i + fi * w2r;
            fr = t;
        }
    }

    // ---- cross-warp reduction (8 partials per point) ----
    sy[w][lane] = make_float2(yr, yi);
    __syncthreads();

    if (tid < PTS) {
        float2 acc = sy[0][tid];
        #pragma unroll
        for (int ww = 1; ww < NWARP; ++ww) {
            acc.x += sy[ww][tid].x;
            acc.y += sy[ww][tid].y;
        }
        const int mo = mblk * PTS + tid;
        if (real_only) {
            out[b * M_DIM + mo] = acc.x;
        } else {
            reinterpret_cast<float2*>(out)[b * M_DIM + mo] = acc;
        }
    }
}

extern "C" void kernel_launch(void* const* d_in, const int* in_sizes, int n_in,
                              void* d_out, int out_size) {
    // Select inputs by element count (metadata order may differ):
    //   x: 2*8192*2 = 32768, f_hat: 2*64*64 = 8192
    const float* x;
    const float* f_hat;
    if (in_sizes[0] == B_DIM * M_DIM * 2) {
        x = (const float*)d_in[0];
        f_hat = (const float*)d_in[1];
    } else {
        x = (const float*)d_in[1];
        f_hat = (const float*)d_in[0];
    }

    float* out = (float*)d_out;
    const int real_only = (out_size == B_DIM * M_DIM) ? 1 : 0;

    ndft_kernel<<<B_DIM * BLOCKS_PER_B, TPB>>>(x, f_hat, out, real_only);
}